// round 12
// baseline (speedup 1.0000x reference)
#include <cuda_runtime.h>
#include <math.h>
#include <stdint.h>

#define T_TOK 8192
#define D_IN  512
#define H_HID 1024
#define NE    16
#define NA    (T_TOK * 2)          // 16384 assignments

#define BM 128
#define BN 128
#define BK 16
#define MAX_TILES (NA / BM + NE)   // 144

#define ASTRIDE 20                  // A smem row stride (floats): LDSM conflict-free (5r+c mod 8)
#define BSTRIDE 136                 // B smem row stride (floats): frag reads conflict-free
#define A_STAGE (BM * ASTRIDE)      // 2560 floats
#define B_STAGE (BK * BSTRIDE)      // 2176 floats

// ---------------- scratch (device globals: no allocations allowed) ----------
// NOTE: never passed as kernel arguments from host (host-side &g_x is the host
// shadow, silently writable via ATS on GB300!). Always referenced in device code.
__device__ float g_h[(size_t)NA * H_HID];
__device__ float g_o[(size_t)NA * D_IN];
__device__ int   g_counts[NE];
__device__ int   g_cursor[NE];
__device__ int   g_offsets[NE + 1];
__device__ int   g_bucket_tok[NA];
__device__ int   g_tok_pos[NA];
__device__ float g_tok_w[NA];
__device__ int2  g_tiles[MAX_TILES];
__device__ int   g_ntiles;

__device__ __forceinline__ float gelu_exact(float v) {
    return 0.5f * v * (1.0f + erff(v * 0.70710678118654752f));
}

// ---------------- 0: zero counters -------------------------------------------
__global__ void zero_kernel() {
    int i = threadIdx.x;
    if (i < NE) { g_counts[i] = 0; g_cursor[i] = 0; }
}

// ---------------- 1: router (one warp per token) -----------------------------
__global__ void router_kernel(const float* __restrict__ x,
                              const float* __restrict__ Wr,
                              const float* __restrict__ br) {
    int warp = (blockIdx.x * blockDim.x + threadIdx.x) >> 5;
    int lane = threadIdx.x & 31;
    if (warp >= T_TOK) return;

    const float* xr = x + (size_t)warp * D_IN;
    float acc[NE];
#pragma unroll
    for (int e = 0; e < NE; e++) acc[e] = 0.f;

    for (int d = lane; d < D_IN; d += 32) {
        float xv = xr[d];
        const float* wrow = Wr + d * NE;
#pragma unroll
        for (int e = 0; e < NE; e++) acc[e] += xv * wrow[e];
    }
#pragma unroll
    for (int e = 0; e < NE; e++) {
#pragma unroll
        for (int off = 16; off; off >>= 1)
            acc[e] += __shfl_xor_sync(0xffffffffu, acc[e], off);
    }

    if (lane == 0) {
        float lg[NE];
        float mx = -1e30f;
#pragma unroll
        for (int e = 0; e < NE; e++) { lg[e] = acc[e] + br[e]; mx = fmaxf(mx, lg[e]); }
#pragma unroll
        for (int e = 0; e < NE; e++) lg[e] = expf(lg[e] - mx);

        int   i0 = 0; float p0 = lg[0];
#pragma unroll
        for (int e = 1; e < NE; e++) if (lg[e] > p0) { p0 = lg[e]; i0 = e; }
        int   i1 = -1; float p1 = -1.f;
#pragma unroll
        for (int e = 0; e < NE; e++) if (e != i0 && lg[e] > p1) { p1 = lg[e]; i1 = e; }

        float inv = 1.f / (p0 + p1);
        g_tok_w[warp * 2 + 0] = p0 * inv;
        g_tok_w[warp * 2 + 1] = p1 * inv;
        g_tok_pos[warp * 2 + 0] = i0;   // expert idx for now
        g_tok_pos[warp * 2 + 1] = i1;
        atomicAdd(&g_counts[i0], 1);
        atomicAdd(&g_counts[i1], 1);
    }
}

// ---------------- 2: scan + tile worklist ------------------------------------
__global__ void scan_kernel() {
    if (threadIdx.x != 0) return;
    int off = 0;
    for (int e = 0; e < NE; e++) { g_offsets[e] = off; off += g_counts[e]; }
    g_offsets[NE] = off;
    int nt = 0;
    for (int e = 0; e < NE; e++)
        for (int r = 0; r < g_counts[e]; r += BM)
            g_tiles[nt++] = make_int2(e, g_offsets[e] + r);
    g_ntiles = nt;
}

// ---------------- 3: scatter assignments into expert buckets -----------------
__global__ void scatter_kernel() {
    int i = blockIdx.x * blockDim.x + threadIdx.x;
    if (i >= NA) return;
    int e   = g_tok_pos[i];
    int pos = g_offsets[e] + atomicAdd(&g_cursor[e], 1);
    g_bucket_tok[pos] = i >> 1;
    g_tok_pos[i]      = pos;
}

// ---------------- 4/5: tensor-core GEMM (tf32 mma.sync + ldmatrix A) ---------
// FIRST: A = gathered x rows, Out = g_h, GELU epilogue.
// !FIRST: A = g_h rows,       Out = g_o, bias-only epilogue.
template<int K, int N, bool FIRST>
__global__ __launch_bounds__(256) void mma_gemm(const float* __restrict__ Xarg,
                                                const float* __restrict__ Wbase,
                                                const float* __restrict__ bias) {
    int tile = blockIdx.y;
    if (tile >= g_ntiles) return;
    int e    = g_tiles[tile].x;
    int row0 = g_tiles[tile].y;
    int rows = min(BM, g_offsets[e + 1] - row0);
    int n0   = blockIdx.x * BN;

    const float* Abase = FIRST ? Xarg : (const float*)g_h;  // device-resolved
    float*       Out   = FIRST ? (float*)g_h : (float*)g_o; // device-resolved

    __shared__ float sA[2 * A_STAGE];   // 20.0 KB
    __shared__ float sB[2 * B_STAGE];   // 17.0 KB  -> 37.9 KB static
    uint32_t sA_u = (uint32_t)__cvta_generic_to_shared(sA);
    uint32_t sB_u = (uint32_t)__cvta_generic_to_shared(sB);

    const float* W = Wbase + (size_t)e * K * N;

    int tid  = threadIdx.x;
    int lane = tid & 31;
    int warp = tid >> 5;
    int mw = (warp >> 2) * 64;   // warp m-base within tile
    int nw = (warp & 3) * 32;    // warp n-base within tile
    int g  = lane >> 2;          // mma group id
    int tg = lane & 3;           // thread-in-group

    // ldmatrix lane addressing for 8x4-b32 matrices:
    //   matrix = lane>>3 (0..3); row-in-matrix = lane&7
    //   matrices 0/1 -> k-chunk +0, rows +0/+8; matrices 2/3 -> k-chunk +4
    int lr_off = ((lane >> 3) & 1) * 8 + (lane & 7);  // row offset within 16-row frag
    int lk_off = (lane >> 4) * 4;                     // k offset (0 or 4)

    // ---- A load: 2 threads per row, 2x 16B chunks each (row = 16 floats) ----
    int lm  = tid >> 1;          // row 0..127
    int ac0 = (tid & 1) * 2;     // chunk base 0 or 2
    const float* aptr;
    int asz = 16;
    if (FIRST) {
        int tok = (lm < rows) ? g_bucket_tok[row0 + lm] : -1;
        aptr = Abase + (size_t)(tok < 0 ? 0 : tok) * K;
        if (tok < 0) asz = 0;
    } else {
        aptr = Abase + (size_t)(row0 + (lm < rows ? lm : 0)) * K;
        if (lm >= rows) asz = 0;
    }
    // ---- B load: 16 threads per k-row, 2x 16B chunks each (row = 128 floats) --
    int kb  = tid >> 4;          // k row 0..15
    int bc0 = (tid & 15) * 2;    // chunk base

    float acc[4][4][4] = {};

    const int KT = K / BK;
#define LOAD_STAGE(kt, s)                                                              \
    {                                                                                  \
        int k0 = (kt) * BK;                                                            \
        uint32_t ad = sA_u + ((s) * A_STAGE + lm * ASTRIDE) * 4;                       \
        const float* asrc = aptr + k0;                                                 \
        _Pragma("unroll")                                                              \
        for (int j = 0; j < 2; j++) {                                                  \
            int c = ac0 + j;                                                           \
            asm volatile("cp.async.cg.shared.global [%0], [%1], 16, %2;\n"             \
                         :: "r"(ad + c * 16), "l"(asrc + c * 4), "r"(asz));            \
        }                                                                              \
        uint32_t bd = sB_u + ((s) * B_STAGE + kb * BSTRIDE) * 4;                       \
        const float* bsrc = W + (size_t)(k0 + kb) * N + n0;                            \
        _Pragma("unroll")                                                              \
        for (int j = 0; j < 2; j++) {                                                  \
            int c = bc0 + j;                                                           \
            asm volatile("cp.async.cg.shared.global [%0], [%1], 16;\n"                 \
                         :: "r"(bd + c * 16), "l"(bsrc + c * 4));                      \
        }                                                                              \
        asm volatile("cp.async.commit_group;\n");                                      \
    }

    LOAD_STAGE(0, 0)
    for (int kt = 0; kt < KT; kt++) {
        int s = kt & 1;
        if (kt + 1 < KT) {
            LOAD_STAGE(kt + 1, s ^ 1)
            asm volatile("cp.async.wait_group 1;\n");
        } else {
            asm volatile("cp.async.wait_group 0;\n");
        }
        __syncthreads();

        uint32_t Ast_u = sA_u + s * A_STAGE * 4;
        const float* Bst = sB + s * B_STAGE;
#pragma unroll
        for (int ks = 0; ks < 2; ks++) {
            // A frags via ldmatrix.x4: one instruction covers a0..a3 of a 16x8 tile.
            uint32_t a[4][4];
#pragma unroll
            for (int mt = 0; mt < 4; mt++) {
                int r = mw + mt * 16 + lr_off;
                int kc = ks * 8 + lk_off;
                uint32_t addr = Ast_u + (r * ASTRIDE + kc) * 4;
                asm volatile("ldmatrix.sync.aligned.m8n8.x4.shared.b16 {%0,%1,%2,%3}, [%4];\n"
                             : "=r"(a[mt][0]), "=r"(a[mt][1]), "=r"(a[mt][2]), "=r"(a[mt][3])
                             : "r"(addr));
            }
            // B frag: b0=(k,n) b1=(k+4,n), k=ks*8+tg, n=nw+nt*8+g
            uint32_t b[4][2];
            int kk = ks * 8 + tg;
#pragma unroll
            for (int nt = 0; nt < 4; nt++) {
                int nn = nw + nt * 8 + g;
                b[nt][0] = __float_as_uint(Bst[kk * BSTRIDE + nn]);
                b[nt][1] = __float_as_uint(Bst[(kk + 4) * BSTRIDE + nn]);
            }
#pragma unroll
            for (int mt = 0; mt < 4; mt++)
#pragma unroll
                for (int nt = 0; nt < 4; nt++) {
                    asm volatile(
                        "mma.sync.aligned.m16n8k8.row.col.f32.tf32.tf32.f32 "
                        "{%0,%1,%2,%3}, {%4,%5,%6,%7}, {%8,%9}, {%0,%1,%2,%3};\n"
                        : "+f"(acc[mt][nt][0]), "+f"(acc[mt][nt][1]),
                          "+f"(acc[mt][nt][2]), "+f"(acc[mt][nt][3])
                        : "r"(a[mt][0]), "r"(a[mt][1]), "r"(a[mt][2]), "r"(a[mt][3]),
                          "r"(b[nt][0]), "r"(b[nt][1]));
                }
        }
        __syncthreads();
    }
#undef LOAD_STAGE

    // ---- epilogue: bias (+GELU for FIRST), store ----
    const float* bv = bias + (size_t)e * N + n0;
#pragma unroll
    for (int nt = 0; nt < 4; nt++) {
        int col = nw + nt * 8 + tg * 2;
        float2 bb = *(const float2*)&bv[col];
#pragma unroll
        for (int mt = 0; mt < 4; mt++) {
            int lr = mw + mt * 16 + g;
#pragma unroll
            for (int h = 0; h < 2; h++) {
                int r = lr + h * 8;
                if (r < rows) {
                    float2 o;
                    o.x = acc[mt][nt][2 * h + 0] + bb.x;
                    o.y = acc[mt][nt][2 * h + 1] + bb.y;
                    if (FIRST) { o.x = gelu_exact(o.x); o.y = gelu_exact(o.y); }
                    *(float2*)&Out[(size_t)(row0 + r) * N + n0 + col] = o;
                }
            }
        }
    }
}

// ---------------- 6: combine + residual (deterministic gather) ---------------
__global__ void combine_kernel(const float* __restrict__ x, float* __restrict__ out) {
    int t = blockIdx.x;
    int d = threadIdx.x * 4;
    float w0 = g_tok_w[2 * t + 0], w1 = g_tok_w[2 * t + 1];
    int   p0 = g_tok_pos[2 * t + 0], p1 = g_tok_pos[2 * t + 1];
    float4 xv = *(const float4*)&x[(size_t)t * D_IN + d];
    float4 o0 = *(const float4*)&g_o[(size_t)p0 * D_IN + d];
    float4 o1 = *(const float4*)&g_o[(size_t)p1 * D_IN + d];
    float4 r;
    r.x = xv.x + w0 * o0.x + w1 * o1.x;
    r.y = xv.y + w0 * o0.y + w1 * o1.y;
    r.z = xv.z + w0 * o0.z + w1 * o1.z;
    r.w = xv.w + w0 * o0.w + w1 * o1.w;
    *(float4*)&out[(size_t)t * D_IN + d] = r;
}

// ---------------- launch ------------------------------------------------------
extern "C" void kernel_launch(void* const* d_in, const int* in_sizes, int n_in,
                              void* d_out, int out_size) {
    const float* x  = (const float*)d_in[0];
    const float* Wr = (const float*)d_in[1];
    const float* br = (const float*)d_in[2];
    const float* W1 = (const float*)d_in[3];
    const float* b1 = (const float*)d_in[4];
    const float* W2 = (const float*)d_in[5];
    const float* b2 = (const float*)d_in[6];
    float* out = (float*)d_out;

    zero_kernel<<<1, 32>>>();
    router_kernel<<<T_TOK / 8, 256>>>(x, Wr, br);
    scan_kernel<<<1, 32>>>();
    scatter_kernel<<<(NA + 255) / 256, 256>>>();
    mma_gemm<D_IN, H_HID, true><<<dim3(H_HID / BN, MAX_TILES), 256>>>(x, W1, b1);
    mma_gemm<H_HID, D_IN, false><<<dim3(D_IN / BN, MAX_TILES), 256>>>(nullptr, W2, b2);
    combine_kernel<<<T_TOK, 128>>>(x, out);
}

// round 14
// speedup vs baseline: 1.0460x; 1.0460x over previous
#include <cuda_runtime.h>
#include <math.h>
#include <stdint.h>

#define T_TOK 8192
#define D_IN  512
#define H_HID 1024
#define NE    16
#define NA    (T_TOK * 2)          // 16384 assignments

#define BM 128
#define BN 128
#define BK 16
#define STAGES 4
#define MAX_TILES (NA / BM + NE)   // 144

#define ASTRIDE 20                  // A smem row stride (floats)
#define BSTRIDE 136                 // B smem row stride (floats)
#define A_STAGE (BM * ASTRIDE)      // 2560 floats
#define B_STAGE (BK * BSTRIDE)      // 2176 floats
#define SMEM_BYTES (STAGES * (A_STAGE + B_STAGE) * 4)   // 75776 B

// ---------------- scratch (device globals: no allocations allowed) ----------
// NOTE: never passed as kernel arguments from host (host-side &g_x is the host
// shadow, silently writable via ATS on GB300!). Always referenced in device code.
__device__ float g_h[(size_t)NA * H_HID];
__device__ float g_o[(size_t)NA * D_IN];
__device__ int   g_counts[NE];
__device__ int   g_cursor[NE];
__device__ int   g_offsets[NE + 1];
__device__ int   g_bucket_tok[NA];
__device__ int   g_tok_pos[NA];
__device__ float g_tok_w[NA];
__device__ int2  g_tiles[MAX_TILES];
__device__ int   g_ntiles;

__device__ __forceinline__ float gelu_exact(float v) {
    return 0.5f * v * (1.0f + erff(v * 0.70710678118654752f));
}

// ---------------- 0: zero counters -------------------------------------------
__global__ void zero_kernel() {
    int i = threadIdx.x;
    if (i < NE) { g_counts[i] = 0; g_cursor[i] = 0; }
}

// ---------------- 1: router (one warp per token) -----------------------------
__global__ void router_kernel(const float* __restrict__ x,
                              const float* __restrict__ Wr,
                              const float* __restrict__ br) {
    int warp = (blockIdx.x * blockDim.x + threadIdx.x) >> 5;
    int lane = threadIdx.x & 31;
    if (warp >= T_TOK) return;

    const float* xr = x + (size_t)warp * D_IN;
    float acc[NE];
#pragma unroll
    for (int e = 0; e < NE; e++) acc[e] = 0.f;

    for (int d = lane; d < D_IN; d += 32) {
        float xv = xr[d];
        const float* wrow = Wr + d * NE;
#pragma unroll
        for (int e = 0; e < NE; e++) acc[e] += xv * wrow[e];
    }
#pragma unroll
    for (int e = 0; e < NE; e++) {
#pragma unroll
        for (int off = 16; off; off >>= 1)
            acc[e] += __shfl_xor_sync(0xffffffffu, acc[e], off);
    }

    if (lane == 0) {
        float lg[NE];
        float mx = -1e30f;
#pragma unroll
        for (int e = 0; e < NE; e++) { lg[e] = acc[e] + br[e]; mx = fmaxf(mx, lg[e]); }
#pragma unroll
        for (int e = 0; e < NE; e++) lg[e] = expf(lg[e] - mx);

        int   i0 = 0; float p0 = lg[0];
#pragma unroll
        for (int e = 1; e < NE; e++) if (lg[e] > p0) { p0 = lg[e]; i0 = e; }
        int   i1 = -1; float p1 = -1.f;
#pragma unroll
        for (int e = 0; e < NE; e++) if (e != i0 && lg[e] > p1) { p1 = lg[e]; i1 = e; }

        float inv = 1.f / (p0 + p1);
        g_tok_w[warp * 2 + 0] = p0 * inv;
        g_tok_w[warp * 2 + 1] = p1 * inv;
        g_tok_pos[warp * 2 + 0] = i0;   // expert idx for now
        g_tok_pos[warp * 2 + 1] = i1;
        atomicAdd(&g_counts[i0], 1);
        atomicAdd(&g_counts[i1], 1);
    }
}

// ---------------- 2: scan + tile worklist ------------------------------------
__global__ void scan_kernel() {
    if (threadIdx.x != 0) return;
    int off = 0;
    for (int e = 0; e < NE; e++) { g_offsets[e] = off; off += g_counts[e]; }
    g_offsets[NE] = off;
    int nt = 0;
    for (int e = 0; e < NE; e++)
        for (int r = 0; r < g_counts[e]; r += BM)
            g_tiles[nt++] = make_int2(e, g_offsets[e] + r);
    g_ntiles = nt;
}

// ---------------- 3: scatter assignments into expert buckets -----------------
__global__ void scatter_kernel() {
    int i = blockIdx.x * blockDim.x + threadIdx.x;
    if (i >= NA) return;
    int e   = g_tok_pos[i];
    int pos = g_offsets[e] + atomicAdd(&g_cursor[e], 1);
    g_bucket_tok[pos] = i >> 1;
    g_tok_pos[i]      = pos;
}

// ---------------- 4/5: tensor-core GEMM (tf32 mma.sync, 4-stage ring) --------
// FIRST: A = gathered x rows, Out = g_h, GELU epilogue.
// !FIRST: A = g_h rows,       Out = g_o, bias-only epilogue.
template<int K, int N, bool FIRST>
__global__ __launch_bounds__(256, 2) void mma_gemm(const float* __restrict__ Xarg,
                                                   const float* __restrict__ Wbase,
                                                   const float* __restrict__ bias) {
    int tile = blockIdx.y;
    if (tile >= g_ntiles) return;
    int e    = g_tiles[tile].x;
    int row0 = g_tiles[tile].y;
    int rows = min(BM, g_offsets[e + 1] - row0);
    int n0   = blockIdx.x * BN;

    const float* Abase = FIRST ? Xarg : (const float*)g_h;  // device-resolved
    float*       Out   = FIRST ? (float*)g_h : (float*)g_o; // device-resolved

    extern __shared__ float smem[];
    float* sB = smem + STAGES * A_STAGE;
    uint32_t sA_u = (uint32_t)__cvta_generic_to_shared(smem);
    uint32_t sB_u = (uint32_t)__cvta_generic_to_shared(sB);

    const float* W = Wbase + (size_t)e * K * N;

    int tid  = threadIdx.x;
    int lane = tid & 31;
    int warp = tid >> 5;
    int mw = (warp >> 2) * 64;   // warp m-base within tile
    int nw = (warp & 3) * 32;    // warp n-base within tile
    int g  = lane >> 2;          // mma group id
    int tg = lane & 3;           // thread-in-group

    // ---- A load: 2 threads per row, 2x 16B chunks each (row = 16 floats) ----
    int lm  = tid >> 1;          // row 0..127
    int ac0 = (tid & 1) * 2;     // chunk base 0 or 2
    const float* aptr;
    int asz = 16;
    if (FIRST) {
        int tok = (lm < rows) ? g_bucket_tok[row0 + lm] : -1;
        aptr = Abase + (size_t)(tok < 0 ? 0 : tok) * K;
        if (tok < 0) asz = 0;
    } else {
        aptr = Abase + (size_t)(row0 + (lm < rows ? lm : 0)) * K;
        if (lm >= rows) asz = 0;
    }
    // ---- B load: 16 threads per k-row, 2x 16B chunks each ----
    int kb  = tid >> 4;          // k row 0..15
    int bc0 = (tid & 15) * 2;    // chunk base

    float acc[4][4][4] = {};

    const int KT = K / BK;
#define LOAD_STAGE(kt, s)                                                              \
    {                                                                                  \
        int k0 = (kt) * BK;                                                            \
        uint32_t ad = sA_u + ((s) * A_STAGE + lm * ASTRIDE) * 4;                       \
        const float* asrc = aptr + k0;                                                 \
        _Pragma("unroll")                                                              \
        for (int j = 0; j < 2; j++) {                                                  \
            int c = ac0 + j;                                                           \
            asm volatile("cp.async.cg.shared.global [%0], [%1], 16, %2;\n"             \
                         :: "r"(ad + c * 16), "l"(asrc + c * 4), "r"(asz));            \
        }                                                                              \
        uint32_t bd = sB_u + ((s) * B_STAGE + kb * BSTRIDE) * 4;                       \
        const float* bsrc = W + (size_t)(k0 + kb) * N + n0;                            \
        _Pragma("unroll")                                                              \
        for (int j = 0; j < 2; j++) {                                                  \
            int c = bc0 + j;                                                           \
            asm volatile("cp.async.cg.shared.global [%0], [%1], 16;\n"                 \
                         :: "r"(bd + c * 16), "l"(bsrc + c * 4));                      \
        }                                                                              \
        asm volatile("cp.async.commit_group;\n");                                      \
    }

    // prologue: fill 3 stages (one commit group per stage)
#pragma unroll
    for (int p = 0; p < STAGES - 1; p++) {
        LOAD_STAGE(p, p)
    }

    for (int kt = 0; kt < KT; kt++) {
        int s = kt & (STAGES - 1);
        // retire all but the 2 newest groups -> stage kt resident
        asm volatile("cp.async.wait_group %0;\n" :: "n"(STAGES - 2));
        __syncthreads();

        // issue next stage into the slot freed by iteration kt-1
        if (kt + STAGES - 1 < KT) {
            LOAD_STAGE(kt + STAGES - 1, (kt + STAGES - 1) & (STAGES - 1))
        } else {
            asm volatile("cp.async.commit_group;\n");   // keep group count in lockstep
        }

        const float* Ast = smem + s * A_STAGE;
        const float* Bst = sB + s * B_STAGE;
#pragma unroll
        for (int ks = 0; ks < 2; ks++) {
            // A frag (m16n8k8.tf32): a0=(r,k) a1=(r+8,k) a2=(r,k+4) a3=(r+8,k+4)
            int kA = ks * 8 + tg;
            uint32_t a[4][4];
#pragma unroll
            for (int mt = 0; mt < 4; mt++) {
                int r0_ = mw + mt * 16 + g;
                int r1_ = r0_ + 8;
                a[mt][0] = __float_as_uint(Ast[r0_ * ASTRIDE + kA]);
                a[mt][1] = __float_as_uint(Ast[r1_ * ASTRIDE + kA]);
                a[mt][2] = __float_as_uint(Ast[r0_ * ASTRIDE + kA + 4]);
                a[mt][3] = __float_as_uint(Ast[r1_ * ASTRIDE + kA + 4]);
            }
            // B frag: b0=(k,n) b1=(k+4,n)
            uint32_t b[4][2];
            int kk = ks * 8 + tg;
#pragma unroll
            for (int nt = 0; nt < 4; nt++) {
                int nn = nw + nt * 8 + g;
                b[nt][0] = __float_as_uint(Bst[kk * BSTRIDE + nn]);
                b[nt][1] = __float_as_uint(Bst[(kk + 4) * BSTRIDE + nn]);
            }
#pragma unroll
            for (int mt = 0; mt < 4; mt++)
#pragma unroll
                for (int nt = 0; nt < 4; nt++) {
                    asm volatile(
                        "mma.sync.aligned.m16n8k8.row.col.f32.tf32.tf32.f32 "
                        "{%0,%1,%2,%3}, {%4,%5,%6,%7}, {%8,%9}, {%0,%1,%2,%3};\n"
                        : "+f"(acc[mt][nt][0]), "+f"(acc[mt][nt][1]),
                          "+f"(acc[mt][nt][2]), "+f"(acc[mt][nt][3])
                        : "r"(a[mt][0]), "r"(a[mt][1]), "r"(a[mt][2]), "r"(a[mt][3]),
                          "r"(b[nt][0]), "r"(b[nt][1]));
                }
        }
    }
#undef LOAD_STAGE

    // ---- epilogue: bias (+GELU for FIRST), store ----
    const float* bv = bias + (size_t)e * N + n0;
#pragma unroll
    for (int nt = 0; nt < 4; nt++) {
        int col = nw + nt * 8 + tg * 2;
        float2 bb = *(const float2*)&bv[col];
#pragma unroll
        for (int mt = 0; mt < 4; mt++) {
            int lr = mw + mt * 16 + g;
#pragma unroll
            for (int h = 0; h < 2; h++) {
                int r = lr + h * 8;
                if (r < rows) {
                    float2 o;
                    o.x = acc[mt][nt][2 * h + 0] + bb.x;
                    o.y = acc[mt][nt][2 * h + 1] + bb.y;
                    if (FIRST) { o.x = gelu_exact(o.x); o.y = gelu_exact(o.y); }
                    *(float2*)&Out[(size_t)(row0 + r) * N + n0 + col] = o;
                }
            }
        }
    }
}

// ---------------- 6: combine + residual (deterministic gather) ---------------
__global__ void combine_kernel(const float* __restrict__ x, float* __restrict__ out) {
    int t = blockIdx.x;
    int d = threadIdx.x * 4;
    float w0 = g_tok_w[2 * t + 0], w1 = g_tok_w[2 * t + 1];
    int   p0 = g_tok_pos[2 * t + 0], p1 = g_tok_pos[2 * t + 1];
    float4 xv = *(const float4*)&x[(size_t)t * D_IN + d];
    float4 o0 = *(const float4*)&g_o[(size_t)p0 * D_IN + d];
    float4 o1 = *(const float4*)&g_o[(size_t)p1 * D_IN + d];
    float4 r;
    r.x = xv.x + w0 * o0.x + w1 * o1.x;
    r.y = xv.y + w0 * o0.y + w1 * o1.y;
    r.z = xv.z + w0 * o0.z + w1 * o1.z;
    r.w = xv.w + w0 * o0.w + w1 * o1.w;
    *(float4*)&out[(size_t)t * D_IN + d] = r;
}

// ---------------- launch ------------------------------------------------------
extern "C" void kernel_launch(void* const* d_in, const int* in_sizes, int n_in,
                              void* d_out, int out_size) {
    const float* x  = (const float*)d_in[0];
    const float* Wr = (const float*)d_in[1];
    const float* br = (const float*)d_in[2];
    const float* W1 = (const float*)d_in[3];
    const float* b1 = (const float*)d_in[4];
    const float* W2 = (const float*)d_in[5];
    const float* b2 = (const float*)d_in[6];
    float* out = (float*)d_out;

    cudaFuncSetAttribute(mma_gemm<D_IN, H_HID, true>,
                         cudaFuncAttributeMaxDynamicSharedMemorySize, SMEM_BYTES);
    cudaFuncSetAttribute(mma_gemm<H_HID, D_IN, false>,
                         cudaFuncAttributeMaxDynamicSharedMemorySize, SMEM_BYTES);

    zero_kernel<<<1, 32>>>();
    router_kernel<<<T_TOK / 8, 256>>>(x, Wr, br);
    scan_kernel<<<1, 32>>>();
    scatter_kernel<<<(NA + 255) / 256, 256>>>();
    mma_gemm<D_IN, H_HID, true><<<dim3(H_HID / BN, MAX_TILES), 256, SMEM_BYTES>>>(x, W1, b1);
    mma_gemm<H_HID, D_IN, false><<<dim3(D_IN / BN, MAX_TILES), 256, SMEM_BYTES>>>(nullptr, W2, b2);
    combine_kernel<<<T_TOK, 128>>>(x, out);
}